// round 11
// baseline (speedup 1.0000x reference)
#include <cuda_runtime.h>
#include <cuda_bf16.h>
#include <math.h>
#include <stdint.h>

// Problem constants
#define BB  2
#define SSQ 2048
#define HH  768
#define NHH 12
#define FFD 3072
#define LLN 2
#define DHH 64
#define MMR (BB*SSQ)          // 4096 rows

#define NEGV (-10000.0f)
#define SPLITK 4

// ---------------- scratch (device globals; no allocation allowed) -------------
__device__ float g_v    [BB*SSQ*HH];
__device__ float g_attn [(size_t)SPLITK*MMR*HH];   // split-K partial slabs
__device__ float g_xmid [BB*SSQ*HH];
__device__ float g_ffn  [(size_t)SPLITK*MMR*HH];   // split-K partial slabs
__device__ float g_x    [BB*SSQ*HH];
// bf16 hi/lo activation buffers
__device__ __nv_bfloat16 g_xh  [(size_t)MMR*HH];
__device__ __nv_bfloat16 g_xl  [(size_t)MMR*HH];
__device__ __nv_bfloat16 g_qh  [(size_t)MMR*HH];
__device__ __nv_bfloat16 g_ql  [(size_t)MMR*HH];
__device__ __nv_bfloat16 g_kh  [(size_t)MMR*HH];
__device__ __nv_bfloat16 g_kl  [(size_t)MMR*HH];
__device__ __nv_bfloat16 g_ctxh[(size_t)MMR*HH];
__device__ __nv_bfloat16 g_ctxl[(size_t)MMR*HH];
__device__ __nv_bfloat16 g_xmh [(size_t)MMR*HH];
__device__ __nv_bfloat16 g_xml [(size_t)MMR*HH];
__device__ __nv_bfloat16 g_inth[(size_t)MMR*FFD];
__device__ __nv_bfloat16 g_intl[(size_t)MMR*FFD];
__device__ __nv_bfloat16 g_vth [(size_t)BB*NHH*DHH*SSQ];
__device__ __nv_bfloat16 g_vtl [(size_t)BB*NHH*DHH*SSQ];
// bf16 hi/lo weight buffers (transposed [N,K]) — reused across layers
__device__ __nv_bfloat16 g_wqkvh[(size_t)3*HH*HH];
__device__ __nv_bfloat16 g_wqkvl[(size_t)3*HH*HH];
__device__ __nv_bfloat16 g_woh [(size_t)HH*HH];
__device__ __nv_bfloat16 g_wol [(size_t)HH*HH];
__device__ __nv_bfloat16 g_wih [(size_t)FFD*HH];
__device__ __nv_bfloat16 g_wil [(size_t)FFD*HH];
__device__ __nv_bfloat16 g_wo2h[(size_t)HH*FFD];
__device__ __nv_bfloat16 g_wo2l[(size_t)HH*FFD];

// ====================== low-level helpers =====================================
__device__ __forceinline__ uint32_t smem_u32(const void* p) {
    uint32_t a;
    asm("{ .reg .u64 t; cvta.to.shared.u64 t, %1; cvt.u32.u64 %0, t; }"
        : "=r"(a) : "l"(p));
    return a;
}
__device__ __forceinline__ void cpasync16(uint32_t dst, const void* src) {
    asm volatile("cp.async.cg.shared.global [%0], [%1], 16;\n"
                 :: "r"(dst), "l"(src) : "memory");
}
#define CP_COMMIT() asm volatile("cp.async.commit_group;\n" ::: "memory")
__device__ __forceinline__ void cp_wait(int n) {
    if (n == 0)      asm volatile("cp.async.wait_group 0;\n" ::: "memory");
    else if (n == 1) asm volatile("cp.async.wait_group 1;\n" ::: "memory");
    else             asm volatile("cp.async.wait_group 2;\n" ::: "memory");
}
__device__ __forceinline__ void ldm_x4(uint32_t& r0, uint32_t& r1,
                                       uint32_t& r2, uint32_t& r3, uint32_t addr) {
    asm volatile("ldmatrix.sync.aligned.m8n8.x4.shared.b16 {%0,%1,%2,%3}, [%4];"
                 : "=r"(r0), "=r"(r1), "=r"(r2), "=r"(r3) : "r"(addr));
}
__device__ __forceinline__ void mma_bf16(float* c, const uint32_t* a, const uint32_t* b) {
    asm volatile(
        "mma.sync.aligned.m16n8k16.row.col.f32.bf16.bf16.f32 "
        "{%0,%1,%2,%3}, {%4,%5,%6,%7}, {%8,%9}, {%0,%1,%2,%3};"
        : "+f"(c[0]), "+f"(c[1]), "+f"(c[2]), "+f"(c[3])
        : "r"(a[0]), "r"(a[1]), "r"(a[2]), "r"(a[3]), "r"(b[0]), "r"(b[1]));
}
__device__ __forceinline__ float gelu_f(float v) {
    return 0.5f * v * (1.0f + erff(v * 0.70710678118654752f));
}
// pack two floats into bf16x2 hi + residual lo
__device__ __forceinline__ void pack_hl(float x, float y, uint32_t& hi, uint32_t& lo) {
    __nv_bfloat162 h = __floats2bfloat162_rn(x, y);
    float hx = __bfloat162float(h.x), hy = __bfloat162float(h.y);
    __nv_bfloat162 l = __floats2bfloat162_rn(x - hx, y - hy);
    hi = *reinterpret_cast<uint32_t*>(&h);
    lo = *reinterpret_cast<uint32_t*>(&l);
}

// ================ convert kernels =============================================
__global__ void __launch_bounds__(256) convert_act(
    const float* __restrict__ x, __nv_bfloat16* __restrict__ hi,
    __nv_bfloat16* __restrict__ lo, int n4)
{
    int i = blockIdx.x * 256 + threadIdx.x;
    if (i >= n4) return;
    float4 v = reinterpret_cast<const float4*>(x)[i];
    uint32_t h0, l0, h1, l1;
    pack_hl(v.x, v.y, h0, l0);
    pack_hl(v.z, v.w, h1, l1);
    reinterpret_cast<uint32_t*>(hi)[i * 2 + 0] = h0;
    reinterpret_cast<uint32_t*>(hi)[i * 2 + 1] = h1;
    reinterpret_cast<uint32_t*>(lo)[i * 2 + 0] = l0;
    reinterpret_cast<uint32_t*>(lo)[i * 2 + 1] = l1;
}

// All 6 weight matrices of one layer, transposed to [N,K] bf16 hi/lo, one launch.
#define CW_BLOCKS 6912
__global__ void __launch_bounds__(256) convert_weights(
    const float* __restrict__ Wq, const float* __restrict__ Wk,
    const float* __restrict__ Wv, const float* __restrict__ Wo,
    const float* __restrict__ Wi, const float* __restrict__ Wo2,
    __nv_bfloat16* __restrict__ wqkvh, __nv_bfloat16* __restrict__ wqkvl,
    __nv_bfloat16* __restrict__ woh,  __nv_bfloat16* __restrict__ wol,
    __nv_bfloat16* __restrict__ wih,  __nv_bfloat16* __restrict__ wil,
    __nv_bfloat16* __restrict__ wo2h, __nv_bfloat16* __restrict__ wo2l)
{
    __shared__ float t[32][33];
    int b = blockIdx.x;
    const float* W; __nv_bfloat16 *Hd, *Ld; int K, N, tix;
    if (b < 1728) {
        int m = b / 576;
        W = (m == 0) ? Wq : (m == 1) ? Wk : Wv;
        Hd = wqkvh + (size_t)m * HH * HH; Ld = wqkvl + (size_t)m * HH * HH;
        K = HH; N = HH; tix = b % 576;
    } else if (b < 2304) {
        W = Wo; Hd = woh; Ld = wol; K = HH; N = HH; tix = b - 1728;
    } else if (b < 4608) {
        W = Wi; Hd = wih; Ld = wil; K = HH; N = FFD; tix = b - 2304;
    } else {
        W = Wo2; Hd = wo2h; Ld = wo2l; K = FFD; N = HH; tix = b - 4608;
    }
    int ntn = N / 32;
    int n0 = (tix % ntn) * 32, k0 = (tix / ntn) * 32;
    int tx = threadIdx.x & 31, ty = threadIdx.x >> 5;   // ty 0..7
    #pragma unroll
    for (int j = 0; j < 4; j++)
        t[ty + 8 * j][tx] = W[(size_t)(k0 + ty + 8 * j) * N + n0 + tx];
    __syncthreads();
    #pragma unroll
    for (int j = 0; j < 4; j++) {
        int n = ty + 8 * j;
        float v = t[tx][n];
        __nv_bfloat16 h = __float2bfloat16(v);
        __nv_bfloat16 l = __float2bfloat16(v - __bfloat162float(h));
        Hd[(size_t)(n0 + n) * K + k0 + tx] = h;
        Ld[(size_t)(n0 + n) * K + k0 + tx] = l;
    }
}

// V [B,S,H] fp32 -> per-head transposed Vt [bh][d][S] bf16 hi/lo
__global__ void __launch_bounds__(256) convert_vT(
    const float* __restrict__ v, __nv_bfloat16* __restrict__ vth,
    __nv_bfloat16* __restrict__ vtl)
{
    __shared__ float t[32][33];
    int bh = blockIdx.z;
    int b = bh / NHH, h = bh % NHH;
    int s0 = blockIdx.x * 32, d0 = blockIdx.y * 32;
    int tx = threadIdx.x & 31, ty = threadIdx.x >> 5;
    #pragma unroll
    for (int j = 0; j < 4; j++)
        t[ty + 8 * j][tx] = v[(size_t)(b * SSQ + s0 + ty + 8 * j) * HH + h * DHH + d0 + tx];
    __syncthreads();
    #pragma unroll
    for (int j = 0; j < 4; j++) {
        int d = ty + 8 * j;
        float val = t[tx][d];
        __nv_bfloat16 hb = __float2bfloat16(val);
        __nv_bfloat16 lb = __float2bfloat16(val - __bfloat162float(hb));
        size_t o = ((size_t)bh * DHH + d0 + d) * SSQ + s0 + tx;
        vth[o] = hb;
        vtl[o] = lb;
    }
}

// ================ mma.sync GEMM (bf16 split, 3 passes) ========================
// Block 128x256, 8 warps (2x4), warp tile 64x64, K chunks of 32, 3-stage pipeline.
// OUT=0: raw fp32 partial -> Cf + z*MMR*N (split-K via gridDim.z; no bias)
// OUT=1: bias + GELU -> bf16 hi/lo (Ch/Cl), stride N
// OUT=2: fused QKV (N=2304): region 0 -> Ch/Cl (Q), 1 -> C2h/C2l (K), 2 -> Cf (V)
static constexpr int GS_ROWB   = 80;                 // 32 bf16 + 16B pad
static constexpr int GS_ATILE  = 128 * GS_ROWB;      // 10240
static constexpr int GS_BTILE  = 256 * GS_ROWB;      // 20480
static constexpr int GS_STAGE  = GS_ATILE + GS_BTILE;// 30720
static constexpr int GS_STAGES = 3;
static constexpr int GT_SMEM   = GS_STAGES * GS_STAGE;  // 92160

template <int OUT>
__global__ void __launch_bounds__(256) gemm_tc(
    const __nv_bfloat16* __restrict__ Ah, const __nv_bfloat16* __restrict__ Al,
    const __nv_bfloat16* __restrict__ BhT, const __nv_bfloat16* __restrict__ BlT,
    const float* __restrict__ b0p, const float* __restrict__ b1p,
    const float* __restrict__ b2p,
    float* __restrict__ Cf,
    __nv_bfloat16* __restrict__ Ch, __nv_bfloat16* __restrict__ Cl,
    __nv_bfloat16* __restrict__ C2h, __nv_bfloat16* __restrict__ C2l,
    int K, int N)
{
    extern __shared__ char smem[];
    const uint32_t sbase = smem_u32(smem);
    const int tid = threadIdx.x;
    const int wid = tid >> 5, lane = tid & 31;
    const int warp_m = wid >> 2, warp_n = wid & 3;   // 2 x 4, warp tile 64x64
    const int m0 = blockIdx.y * 128, n0 = blockIdx.x * 256;

    const int Kl = K / (int)gridDim.z;
    const int kb = (int)blockIdx.z * Kl;
    const int kch = Kl >> 5;
    const int nc = 3 * kch;
    const int seg = tid & 3;
    const int row0 = tid >> 2;       // 0..63

    auto loadChunk = [&](int c) {
        int p = c / kch;
        int kc = kb + ((c - p * kch) << 5);
        const __nv_bfloat16* aS = (p < 2) ? Ah : Al;
        const __nv_bfloat16* bS = (p == 1) ? BlT : BhT;
        uint32_t st = sbase + (uint32_t)(c % GS_STAGES) * GS_STAGE;
        #pragma unroll
        for (int i = 0; i < 2; i++) {
            int r = row0 + i * 64;
            cpasync16(st + (uint32_t)(r * GS_ROWB + seg * 16),
                      (const char*)(aS + (size_t)(m0 + r) * K + kc) + seg * 16);
        }
        #pragma unroll
        for (int i = 0; i < 4; i++) {
            int r = row0 + i * 64;
            cpasync16(st + GS_ATILE + (uint32_t)(r * GS_ROWB + seg * 16),
                      (const char*)(bS + (size_t)(n0 + r) * K + kc) + seg * 16);
        }
        CP_COMMIT();
    };

    float acc[4][8][4];
    #pragma unroll
    for (int mt = 0; mt < 4; mt++)
        #pragma unroll
        for (int nt = 0; nt < 8; nt++)
            #pragma unroll
            for (int r = 0; r < 4; r++) acc[mt][nt][r] = 0.0f;

    loadChunk(0);
    loadChunk(1);

    const int a_row_in_tile = lane & 15;
    const int a_k8 = (lane >> 4) * 8;
    const int b_row_sel = (lane & 7) + ((lane >> 4) & 1) * 8;
    const int b_k8 = (lane & 8) ? 8 : 0;

    for (int c = 0; c < nc; c++) {
        if (c + 2 < nc) loadChunk(c + 2);
        cp_wait((c + 2 < nc) ? 2 : ((c + 1 < nc) ? 1 : 0));
        __syncthreads();

        uint32_t as = sbase + (uint32_t)(c % GS_STAGES) * GS_STAGE;
        uint32_t bs = as + GS_ATILE;

        #pragma unroll
        for (int ks = 0; ks < 2; ks++) {
            uint32_t af[4][4], bf[8][2];
            #pragma unroll
            for (int mt = 0; mt < 4; mt++) {
                uint32_t addr = as
                    + (uint32_t)((warp_m * 64 + mt * 16 + a_row_in_tile) * GS_ROWB)
                    + (uint32_t)((ks * 16 + a_k8) * 2);
                ldm_x4(af[mt][0], af[mt][1], af[mt][2], af[mt][3], addr);
            }
            #pragma unroll
            for (int nt2 = 0; nt2 < 4; nt2++) {
                uint32_t addr = bs
                    + (uint32_t)((warp_n * 64 + nt2 * 16 + b_row_sel) * GS_ROWB)
                    + (uint32_t)((ks * 16 + b_k8) * 2);
                ldm_x4(bf[nt2 * 2][0], bf[nt2 * 2][1],
                       bf[nt2 * 2 + 1][0], bf[nt2 * 2 + 1][1], addr);
            }
            #pragma unroll
            for (int mt = 0; mt < 4; mt++)
                #pragma unroll
                for (int nt = 0; nt < 8; nt++)
                    mma_bf16(acc[mt][nt], af[mt], bf[nt]);
        }
        __syncthreads();
    }

    const int cg = (lane & 3) * 2;
    const int rg = lane >> 2;

    if (OUT == 2) {
        const int reg = n0 / HH;               // 256-tiles never straddle 768-regions
        const float* bp = (reg == 0) ? b0p : (reg == 1) ? b1p : b2p;
        __nv_bfloat16* dh = (reg == 0) ? Ch : C2h;
        __nv_bfloat16* dl = (reg == 0) ? Cl : C2l;
        #pragma unroll
        for (int nt = 0; nt < 8; nt++) {
            int col = n0 + warp_n * 64 + nt * 8 + cg;
            int cl = col - reg * HH;
            float bb0 = bp[cl], bb1 = bp[cl + 1];
            #pragma unroll
            for (int mt = 0; mt < 4; mt++) {
                int r1 = m0 + warp_m * 64 + mt * 16 + rg;
                float v0 = acc[mt][nt][0] + bb0;
                float v1 = acc[mt][nt][1] + bb1;
                float v2 = acc[mt][nt][2] + bb0;
                float v3 = acc[mt][nt][3] + bb1;
                if (reg == 2) {
                    float2 p0; p0.x = v0; p0.y = v1;
                    float2 p1; p1.x = v2; p1.y = v3;
                    *reinterpret_cast<float2*>(Cf + (size_t)r1 * HH + cl) = p0;
                    *reinterpret_cast<float2*>(Cf + (size_t)(r1 + 8) * HH + cl) = p1;
                } else {
                    uint32_t h0, l0, h1, l1;
                    pack_hl(v0, v1, h0, l0);
                    pack_hl(v2, v3, h1, l1);
                    *reinterpret_cast<uint32_t*>(dh + (size_t)r1 * HH + cl) = h0;
                    *reinterpret_cast<uint32_t*>(dl + (size_t)r1 * HH + cl) = l0;
                    *reinterpret_cast<uint32_t*>(dh + (size_t)(r1 + 8) * HH + cl) = h1;
                    *reinterpret_cast<uint32_t*>(dl + (size_t)(r1 + 8) * HH + cl) = l1;
                }
            }
        }
    } else if (OUT == 1) {
        #pragma unroll
        for (int nt = 0; nt < 8; nt++) {
            int col = n0 + warp_n * 64 + nt * 8 + cg;
            float bb0 = b0p[col], bb1 = b0p[col + 1];
            #pragma unroll
            for (int mt = 0; mt < 4; mt++) {
                int r1 = m0 + warp_m * 64 + mt * 16 + rg;
                float v0 = gelu_f(acc[mt][nt][0] + bb0);
                float v1 = gelu_f(acc[mt][nt][1] + bb1);
                float v2 = gelu_f(acc[mt][nt][2] + bb0);
                float v3 = gelu_f(acc[mt][nt][3] + bb1);
                uint32_t h0, l0, h1, l1;
                pack_hl(v0, v1, h0, l0);
                pack_hl(v2, v3, h1, l1);
                *reinterpret_cast<uint32_t*>(Ch + (size_t)r1 * N + col) = h0;
                *reinterpret_cast<uint32_t*>(Cl + (size_t)r1 * N + col) = l0;
                *reinterpret_cast<uint32_t*>(Ch + (size_t)(r1 + 8) * N + col) = h1;
                *reinterpret_cast<uint32_t*>(Cl + (size_t)(r1 + 8) * N + col) = l1;
            }
        }
    } else {
        // OUT == 0: raw split-K partial, no bias; slab per z
        float* Cz = Cf + (size_t)blockIdx.z * MMR * N;
        #pragma unroll
        for (int nt = 0; nt < 8; nt++) {
            int col = n0 + warp_n * 64 + nt * 8 + cg;
            #pragma unroll
            for (int mt = 0; mt < 4; mt++) {
                int r1 = m0 + warp_m * 64 + mt * 16 + rg;
                float2 p0; p0.x = acc[mt][nt][0]; p0.y = acc[mt][nt][1];
                float2 p1; p1.x = acc[mt][nt][2]; p1.y = acc[mt][nt][3];
                *reinterpret_cast<float2*>(Cz + (size_t)r1 * N + col) = p0;
                *reinterpret_cast<float2*>(Cz + (size_t)(r1 + 8) * N + col) = p1;
            }
        }
    }
}

// ================ flash attention (mma.sync, hi/lo split) =====================
#define FA_KSTR 144
#define FA_VSTR 272
#define FA_OFF_KH 0
#define FA_OFF_KL 18432
#define FA_OFF_VH 36864
#define FA_OFF_VL 54272
#define FA_OFF_EXT 71680
#define FA_STAGE 72192
#define FA_SMEM (2*FA_STAGE)

__global__ void __launch_bounds__(256, 1) flash_attn(
    const __nv_bfloat16* __restrict__ qh, const __nv_bfloat16* __restrict__ ql,
    const __nv_bfloat16* __restrict__ kh, const __nv_bfloat16* __restrict__ kl,
    const __nv_bfloat16* __restrict__ vth, const __nv_bfloat16* __restrict__ vtl,
    const float* __restrict__ biasm, const float* __restrict__ mask,
    const float* __restrict__ bcp,
    __nv_bfloat16* __restrict__ ctxh, __nv_bfloat16* __restrict__ ctxl)
{
    extern __shared__ char smem[];
    const uint32_t sbase = smem_u32(smem);
    const int tid = threadIdx.x, wid = tid >> 5, lane = tid & 31;
    const int bh = blockIdx.y, b = bh / NHH, h = bh % NHH;
    const int q0 = blockIdx.x * 128;
    const float bc = bcp[0];

    const int b_row_sel = (lane & 7) + ((lane >> 4) & 1) * 8;
    const int b_k8 = (lane & 8) ? 8 : 0;
    const int colr = 2 * (lane & 3);
    const int rq = q0 + wid * 16 + (lane >> 2);

    uint32_t qhF[4][4], qlF[4][4];
    {
        const __nv_bfloat16* qh0 = qh + (size_t)(b * SSQ + rq) * HH + h * DHH;
        const __nv_bfloat16* ql0 = ql + (size_t)(b * SSQ + rq) * HH + h * DHH;
        const __nv_bfloat16* qh8 = qh0 + 8 * HH;
        const __nv_bfloat16* ql8 = ql0 + 8 * HH;
        #pragma unroll
        for (int f = 0; f < 4; f++) {
            int k = f * 16 + colr;
            qhF[f][0] = *reinterpret_cast<const uint32_t*>(qh0 + k);
            qhF[f][1] = *reinterpret_cast<const uint32_t*>(qh8 + k);
            qhF[f][2] = *reinterpret_cast<const uint32_t*>(qh0 + k + 8);
            qhF[f][3] = *reinterpret_cast<const uint32_t*>(qh8 + k + 8);
            qlF[f][0] = *reinterpret_cast<const uint32_t*>(ql0 + k);
            qlF[f][1] = *reinterpret_cast<const uint32_t*>(ql8 + k);
            qlF[f][2] = *reinterpret_cast<const uint32_t*>(ql0 + k + 8);
            qlF[f][3] = *reinterpret_cast<const uint32_t*>(ql8 + k + 8);
        }
    }

    auto loadTile = [&](int j) {
        uint32_t st = sbase + (uint32_t)(j & 1) * FA_STAGE;
        int k0 = j * 128;
        #pragma unroll
        for (int i = 0; i < 4; i++) {
            int idx = tid + i * 256;
            int row = idx >> 3, seg = idx & 7;
            size_t go = (size_t)(b * SSQ + k0 + row) * HH + h * DHH + seg * 8;
            cpasync16(st + FA_OFF_KH + (uint32_t)(row * FA_KSTR + seg * 16), kh + go);
            cpasync16(st + FA_OFF_KL + (uint32_t)(row * FA_KSTR + seg * 16), kl + go);
        }
        #pragma unroll
        for (int i = 0; i < 4; i++) {
            int idx = tid + i * 256;
            int d = idx >> 4, seg = idx & 15;
            size_t go = ((size_t)bh * DHH + d) * SSQ + k0 + seg * 8;
            cpasync16(st + FA_OFF_VH + (uint32_t)(d * FA_VSTR + seg * 16), vth + go);
            cpasync16(st + FA_OFF_VL + (uint32_t)(d * FA_VSTR + seg * 16), vtl + go);
        }
        if (tid < 128) {
            float mv = mask[b * SSQ + k0 + tid];
            *reinterpret_cast<float*>(smem + (size_t)(j & 1) * FA_STAGE + FA_OFF_EXT + tid * 4)
                = (1.0f - mv) * NEGV;
        }
        CP_COMMIT();
    };

    float m0 = -INFINITY, m1 = -INFINITY, l0 = 0.0f, l1 = 0.0f;
    float oac[8][4];
    #pragma unroll
    for (int nt = 0; nt < 8; nt++)
        #pragma unroll
        for (int r = 0; r < 4; r++) oac[nt][r] = 0.0f;

    const int NT = SSQ / 128;   // 16
    loadTile(0);

    for (int j = 0; j < NT; j++) {
        if (j + 1 < NT) loadTile(j + 1);
        cp_wait((j + 1 < NT) ? 1 : 0);
        __syncthreads();

        uint32_t st = sbase + (uint32_t)(j & 1) * FA_STAGE;
        const float* ext_s = reinterpret_cast<const float*>(
            smem + (size_t)(j & 1) * FA_STAGE + FA_OFF_EXT);
        const int k0 = j * 128;

        float sac[16][4];
        #pragma unroll
        for (int t = 0; t < 16; t++)
            #pragma unroll
            for (int r = 0; r < 4; r++) sac[t][r] = 0.0f;

        #pragma unroll
        for (int pass = 0; pass < 3; pass++) {
            const uint32_t (*AF)[4] = (pass == 2) ? qlF : qhF;
            const uint32_t koff = (pass == 1) ? FA_OFF_KL : FA_OFF_KH;
            #pragma unroll
            for (int ks = 0; ks < 4; ks++) {
                #pragma unroll
                for (int half = 0; half < 2; half++) {
                    uint32_t bb[8][2];
                    #pragma unroll
                    for (int q2 = 0; q2 < 4; q2++) {
                        int nt2 = half * 4 + q2;
                        uint32_t addr = st + koff
                            + (uint32_t)((nt2 * 16 + b_row_sel) * FA_KSTR)
                            + (uint32_t)((ks * 16 + b_k8) * 2);
                        ldm_x4(bb[q2 * 2][0], bb[q2 * 2][1],
                               bb[q2 * 2 + 1][0], bb[q2 * 2 + 1][1], addr);
                    }
                    #pragma unroll
                    for (int t = 0; t < 8; t++)
                        mma_bf16(sac[half * 8 + t], AF[ks], bb[t]);
                }
            }
        }

        #pragma unroll
        for (int t = 0; t < 16; t++) {
            int c = k0 + t * 8 + colr;
            float2 bz0 = *reinterpret_cast<const float2*>(biasm + (size_t)rq * SSQ + c);
            float2 bz1 = *reinterpret_cast<const float2*>(biasm + (size_t)(rq + 8) * SSQ + c);
            float e0 = ext_s[t * 8 + colr], e1 = ext_s[t * 8 + colr + 1];
            sac[t][0] = fmaf(bc, bz0.x, sac[t][0] * 0.125f) + e0;
            sac[t][1] = fmaf(bc, bz0.y, sac[t][1] * 0.125f) + e1;
            sac[t][2] = fmaf(bc, bz1.x, sac[t][2] * 0.125f) + e0;
            sac[t][3] = fmaf(bc, bz1.y, sac[t][3] * 0.125f) + e1;
        }

        float mx0 = -INFINITY, mx1 = -INFINITY;
        #pragma unroll
        for (int t = 0; t < 16; t++) {
            mx0 = fmaxf(mx0, fmaxf(sac[t][0], sac[t][1]));
            mx1 = fmaxf(mx1, fmaxf(sac[t][2], sac[t][3]));
        }
        mx0 = fmaxf(mx0, __shfl_xor_sync(0xffffffffu, mx0, 1));
        mx0 = fmaxf(mx0, __shfl_xor_sync(0xffffffffu, mx0, 2));
        mx1 = fmaxf(mx1, __shfl_xor_sync(0xffffffffu, mx1, 1));
        mx1 = fmaxf(mx1, __shfl_xor_sync(0xffffffffu, mx1, 2));

        float mn0 = fmaxf(m0, mx0), mn1 = fmaxf(m1, mx1);
        float a0 = __expf(m0 - mn0), a1 = __expf(m1 - mn1);
        float s0 = 0.0f, s1 = 0.0f;
        #pragma unroll
        for (int t = 0; t < 16; t++) {
            sac[t][0] = __expf(sac[t][0] - mn0);
            sac[t][1] = __expf(sac[t][1] - mn0);
            sac[t][2] = __expf(sac[t][2] - mn1);
            sac[t][3] = __expf(sac[t][3] - mn1);
            s0 += sac[t][0] + sac[t][1];
            s1 += sac[t][2] + sac[t][3];
        }
        l0 = l0 * a0 + s0;
        l1 = l1 * a1 + s1;
        #pragma unroll
        for (int nt = 0; nt < 8; nt++) {
            oac[nt][0] *= a0; oac[nt][1] *= a0;
            oac[nt][2] *= a1; oac[nt][3] *= a1;
        }
        m0 = mn0; m1 = mn1;

        uint32_t ph[8][4], pl[8][4];
        #pragma unroll
        for (int f = 0; f < 8; f++) {
            int t0 = 2 * f, t1 = 2 * f + 1;
            pack_hl(sac[t0][0], sac[t0][1], ph[f][0], pl[f][0]);
            pack_hl(sac[t0][2], sac[t0][3], ph[f][1], pl[f][1]);
            pack_hl(sac[t1][0], sac[t1][1], ph[f][2], pl[f][2]);
            pack_hl(sac[t1][2], sac[t1][3], ph[f][3], pl[f][3]);
        }

        #pragma unroll
        for (int pass = 0; pass < 3; pass++) {
            const uint32_t (*PF)[4] = (pass == 2) ? pl : ph;
            const uint32_t voff = (pass == 1) ? FA_OFF_VL : FA_OFF_VH;
            #pragma unroll
            for (int f = 0; f < 8; f++) {
                uint32_t vb[8][2];
                #pragma unroll
                for (int q2 = 0; q2 < 4; q2++) {
                    uint32_t addr = st + voff
                        + (uint32_t)((q2 * 16 + b_row_sel) * FA_VSTR)
                        + (uint32_t)((f * 16 + b_k8) * 2);
                    ldm_x4(vb[q2 * 2][0], vb[q2 * 2][1],
                           vb[q2 * 2 + 1][0], vb[q2 * 2 + 1][1], addr);
                }
                #pragma unroll
                for (int nt = 0; nt < 8; nt++)
                    mma_bf16(oac[nt], PF[f], vb[nt]);
            }
        }
        __syncthreads();
    }

    l0 += __shfl_xor_sync(0xffffffffu, l0, 1);
    l0 += __shfl_xor_sync(0xffffffffu, l0, 2);
    l1 += __shfl_xor_sync(0xffffffffu, l1, 1);
    l1 += __shfl_xor_sync(0xffffffffu, l1, 2);
    float i0 = 1.0f / l0, i1 = 1.0f / l1;

    #pragma unroll
    for (int nt = 0; nt < 8; nt++) {
        int col = h * DHH + nt * 8 + colr;
        uint32_t h0, lo0, h1, lo1;
        pack_hl(oac[nt][0] * i0, oac[nt][1] * i0, h0, lo0);
        pack_hl(oac[nt][2] * i1, oac[nt][3] * i1, h1, lo1);
        size_t o0 = (size_t)(b * SSQ + rq) * HH + col;
        size_t o1 = (size_t)(b * SSQ + rq + 8) * HH + col;
        *reinterpret_cast<uint32_t*>(ctxh + o0) = h0;
        *reinterpret_cast<uint32_t*>(ctxl + o0) = lo0;
        *reinterpret_cast<uint32_t*>(ctxh + o1) = h1;
        *reinterpret_cast<uint32_t*>(ctxl + o1) = lo1;
    }
}

// ---------------- block reduction ---------------------------------------------
__device__ __forceinline__ float blockReduceSum(float x) {
    __shared__ float sh[8];
    __syncthreads();
    int lane = threadIdx.x & 31, w = threadIdx.x >> 5;
    #pragma unroll
    for (int o = 16; o > 0; o >>= 1) x += __shfl_xor_sync(0xffffffffu, x, o);
    if (lane == 0) sh[w] = x;
    __syncthreads();
    if (w == 0) {
        x = (lane < 8) ? sh[lane] : 0.0f;
        #pragma unroll
        for (int o = 4; o > 0; o >>= 1) x += __shfl_xor_sync(0xffffffffu, x, o);
        if (lane == 0) sh[0] = x;
    }
    __syncthreads();
    return sh[0];
}

// --- split-K(4) sum + bias + residual + LayerNorm (+ hi/lo emit) --------------
__global__ void __launch_bounds__(256) add_ln4(
    const float* __restrict__ a0, const float* __restrict__ bias,
    const float* __restrict__ res,
    const float* __restrict__ g, const float* __restrict__ bta,
    float* __restrict__ out,
    __nv_bfloat16* __restrict__ oh, __nv_bfloat16* __restrict__ ol)
{
    const int row = blockIdx.x;
    const size_t slab = (size_t)MMR * HH;
    const float* p0 = a0 + (size_t)row * HH;
    const float* p1 = p0 + slab;
    const float* p2 = p1 + slab;
    const float* p3 = p2 + slab;
    const float* rp = res + (size_t)row * HH;
    const int tid = threadIdx.x;

    float v[3];
    float s = 0.0f;
    #pragma unroll
    for (int l = 0; l < 3; l++) {
        int c = tid + l * 256;
        v[l] = ((p0[c] + p1[c]) + (p2[c] + p3[c])) + bias[c] + rp[c];
        s += v[l];
    }
    s = blockReduceSum(s);
    const float mu = s * (1.0f / HH);

    float var = 0.0f;
    #pragma unroll
    for (int l = 0; l < 3; l++) {
        float d = v[l] - mu;
        var += d * d;
    }
    var = blockReduceSum(var);
    const float inv = rsqrtf(var * (1.0f / HH) + 1e-12f);

    float* op = out + (size_t)row * HH;
    __nv_bfloat16* ohp = oh + (size_t)row * HH;
    __nv_bfloat16* olp = ol + (size_t)row * HH;
    #pragma unroll
    for (int l = 0; l < 3; l++) {
        int c = tid + l * 256;
        float y = (v[l] - mu) * inv * g[c] + bta[c];
        op[c] = y;
        __nv_bfloat16 hb = __float2bfloat16(y);
        ohp[c] = hb;
        olp[c] = __float2bfloat16(y - __bfloat162float(hb));
    }
}

// ---------------- host orchestration ------------------------------------------
extern "C" void kernel_launch(void* const* d_in, const int* in_sizes, int n_in,
                              void* d_out, int out_size)
{
    (void)in_sizes; (void)n_in; (void)out_size;

    const float* hidden    = (const float*)d_in[0];
    const float* mask      = (const float*)d_in[1];
    const float* biasm     = (const float*)d_in[2];
    const float* bias_coef = (const float*)d_in[3];
    const float* Wq  = (const float*)d_in[4];
    const float* bq  = (const float*)d_in[5];
    const float* Wk  = (const float*)d_in[6];
    const float* bk  = (const float*)d_in[7];
    const float* Wv  = (const float*)d_in[8];
    const float* bv  = (const float*)d_in[9];
    const float* Wo  = (const float*)d_in[10];
    const float* bo  = (const float*)d_in[11];
    const float* ln1g= (const float*)d_in[12];
    const float* ln1b= (const float*)d_in[13];
    const float* Wi  = (const float*)d_in[14];
    const float* bi  = (const float*)d_in[15];
    const float* Wo2 = (const float*)d_in[16];
    const float* bo2 = (const float*)d_in[17];
    const float* ln2g= (const float*)d_in[18];
    const float* ln2b= (const float*)d_in[19];
    float* out = (float*)d_out;

    cudaFuncSetAttribute(gemm_tc<0>, cudaFuncAttributeMaxDynamicSharedMemorySize, GT_SMEM);
    cudaFuncSetAttribute(gemm_tc<1>, cudaFuncAttributeMaxDynamicSharedMemorySize, GT_SMEM);
    cudaFuncSetAttribute(gemm_tc<2>, cudaFuncAttributeMaxDynamicSharedMemorySize, GT_SMEM);
    cudaFuncSetAttribute(flash_attn, cudaFuncAttributeMaxDynamicSharedMemorySize, FA_SMEM);

    float *vP, *attnP, *xmidP, *ffnP, *xP;
    cudaGetSymbolAddress((void**)&vP,    g_v);
    cudaGetSymbolAddress((void**)&attnP, g_attn);
    cudaGetSymbolAddress((void**)&xmidP, g_xmid);
    cudaGetSymbolAddress((void**)&ffnP,  g_ffn);
    cudaGetSymbolAddress((void**)&xP,    g_x);
    __nv_bfloat16 *xhP,*xlP,*qhP,*qlP,*khP,*klP,*ctxhP,*ctxlP,*xmhP,*xmlP,*inthP,*intlP,*vthP,*vtlP;
    cudaGetSymbolAddress((void**)&xhP,   g_xh);
    cudaGetSymbolAddress((void**)&xlP,   g_xl);
    cudaGetSymbolAddress((void**)&qhP,   g_qh);
    cudaGetSymbolAddress((void**)&qlP,   g_ql);
    cudaGetSymbolAddress((void**)&khP,   g_kh);
    cudaGetSymbolAddress((void**)&klP,   g_kl);
    cudaGetSymbolAddress((void**)&ctxhP, g_ctxh);
    cudaGetSymbolAddress((void**)&ctxlP, g_ctxl);
    cudaGetSymbolAddress((void**)&xmhP,  g_xmh);
    cudaGetSymbolAddress((void**)&xmlP,  g_xml);
    cudaGetSymbolAddress((void**)&inthP, g_inth);
    cudaGetSymbolAddress((void**)&intlP, g_intl);
    cudaGetSymbolAddress((void**)&vthP,  g_vth);
    cudaGetSymbolAddress((void**)&vtlP,  g_vtl);
    __nv_bfloat16 *wqkvh,*wqkvl,*wohP,*wolP,*wihP,*wilP,*wo2hP,*wo2lP;
    cudaGetSymbolAddress((void**)&wqkvh, g_wqkvh);
    cudaGetSymbolAddress((void**)&wqkvl, g_wqkvl);
    cudaGetSymbolAddress((void**)&wohP,  g_woh);
    cudaGetSymbolAddress((void**)&wolP,  g_wol);
    cudaGetSymbolAddress((void**)&wihP,  g_wih);
    cudaGetSymbolAddress((void**)&wilP,  g_wil);
    cudaGetSymbolAddress((void**)&wo2hP, g_wo2h);
    cudaGetSymbolAddress((void**)&wo2lP, g_wo2l);

    // layer-0 input convert
    {
        int n4 = MMR * HH / 4;
        convert_act<<<(n4 + 255) / 256, 256>>>(hidden, xhP, xlP, n4);
    }

    const float* xres = hidden;
    for (int i = 0; i < LLN; i++) {
        const float* Wq_i  = Wq  + (size_t)i * HH * HH;
        const float* Wk_i  = Wk  + (size_t)i * HH * HH;
        const float* Wv_i  = Wv  + (size_t)i * HH * HH;
        const float* Wo_i  = Wo  + (size_t)i * HH * HH;
        const float* Wi_i  = Wi  + (size_t)i * HH * FFD;
        const float* Wo2_i = Wo2 + (size_t)i * FFD * HH;

        // all 6 weight matrices in one launch
        convert_weights<<<CW_BLOCKS, 256>>>(
            Wq_i, Wk_i, Wv_i, Wo_i, Wi_i, Wo2_i,
            wqkvh, wqkvl, wohP, wolP, wihP, wilP, wo2hP, wo2lP);

        // fused QKV projection: N=2304 -> 9 x 32 CTAs
        gemm_tc<2><<<dim3(3*HH/256, MMR/128, 1), 256, GT_SMEM>>>(
            xhP, xlP, wqkvh, wqkvl,
            bq + i*HH, bk + i*HH, bv + i*HH,
            vP, qhP, qlP, khP, klP, HH, 3*HH);

        convert_vT<<<dim3(SSQ/32, DHH/32, BB*NHH), 256>>>(vP, vthP, vtlP);

        flash_attn<<<dim3(SSQ/128, BB*NHH), 256, FA_SMEM>>>(
            qhP, qlP, khP, klP, vthP, vtlP, biasm, mask, bias_coef, ctxhP, ctxlP);

        // output projection, split-K=4 (raw partials into g_attn's 4 slabs)
        gemm_tc<0><<<dim3(HH/256, MMR/128, SPLITK), 256, GT_SMEM>>>(
            ctxhP, ctxlP, wohP, wolP,
            nullptr, nullptr, nullptr,
            attnP, nullptr, nullptr, nullptr, nullptr, HH, HH);
        add_ln4<<<MMR, 256>>>(attnP, bo + i*HH, xres, ln1g + i*HH, ln1b + i*HH,
                              xmidP, xmhP, xmlP);

        // FFN1: N=3072 -> 12 x 32 CTAs
        gemm_tc<1><<<dim3(FFD/256, MMR/128, 1), 256, GT_SMEM>>>(
            xmhP, xmlP, wihP, wilP,
            bi + i*FFD, nullptr, nullptr,
            nullptr, inthP, intlP, nullptr, nullptr, HH, FFD);
        // FFN2: split-K=4
        gemm_tc<0><<<dim3(HH/256, MMR/128, SPLITK), 256, GT_SMEM>>>(
            inthP, intlP, wo2hP, wo2lP,
            nullptr, nullptr, nullptr,
            ffnP, nullptr, nullptr, nullptr, nullptr, FFD, HH);

        float* xo = (i == LLN - 1) ? out : xP;
        add_ln4<<<MMR, 256>>>(ffnP, bo2 + i*HH, xmidP, ln2g + i*HH, ln2b + i*HH,
                              xo, xhP, xlP);
        xres = xo;
    }
}

// round 14
// speedup vs baseline: 1.1121x; 1.1121x over previous
#include <cuda_runtime.h>
#include <cuda_bf16.h>
#include <math.h>
#include <stdint.h>

// Problem constants
#define BB  2
#define SSQ 2048
#define HH  768
#define NHH 12
#define FFD 3072
#define LLN 2
#define DHH 64
#define MMR (BB*SSQ)          // 4096 rows

#define NEGV (-10000.0f)

// ---------------- scratch (device globals; no allocation allowed) -------------
__device__ float g_v    [BB*SSQ*HH];
__device__ float g_attn [(size_t)2*MMR*HH];   // split-K partial slabs
__device__ float g_xmid [BB*SSQ*HH];
__device__ float g_ffn  [(size_t)2*MMR*HH];   // split-K partial slabs
__device__ float g_x    [BB*SSQ*HH];
// bf16 hi/lo activation buffers
__device__ __nv_bfloat16 g_xh  [(size_t)MMR*HH];
__device__ __nv_bfloat16 g_xl  [(size_t)MMR*HH];
__device__ __nv_bfloat16 g_qh  [(size_t)MMR*HH];
__device__ __nv_bfloat16 g_ql  [(size_t)MMR*HH];
__device__ __nv_bfloat16 g_kh  [(size_t)MMR*HH];
__device__ __nv_bfloat16 g_kl  [(size_t)MMR*HH];
__device__ __nv_bfloat16 g_ctxh[(size_t)MMR*HH];
__device__ __nv_bfloat16 g_ctxl[(size_t)MMR*HH];
__device__ __nv_bfloat16 g_xmh [(size_t)MMR*HH];
__device__ __nv_bfloat16 g_xml [(size_t)MMR*HH];
__device__ __nv_bfloat16 g_inth[(size_t)MMR*FFD];
__device__ __nv_bfloat16 g_intl[(size_t)MMR*FFD];
__device__ __nv_bfloat16 g_vth [(size_t)BB*NHH*DHH*SSQ];
__device__ __nv_bfloat16 g_vtl [(size_t)BB*NHH*DHH*SSQ];
// bf16 hi/lo weight buffers (transposed [N,K]) — reused across layers
__device__ __nv_bfloat16 g_wqkvh[(size_t)3*HH*HH];
__device__ __nv_bfloat16 g_wqkvl[(size_t)3*HH*HH];
__device__ __nv_bfloat16 g_woh [(size_t)HH*HH];
__device__ __nv_bfloat16 g_wol [(size_t)HH*HH];
__device__ __nv_bfloat16 g_wih [(size_t)FFD*HH];
__device__ __nv_bfloat16 g_wil [(size_t)FFD*HH];
__device__ __nv_bfloat16 g_wo2h[(size_t)HH*FFD];
__device__ __nv_bfloat16 g_wo2l[(size_t)HH*FFD];

// ====================== low-level helpers =====================================
__device__ __forceinline__ uint32_t smem_u32(const void* p) {
    uint32_t a;
    asm("{ .reg .u64 t; cvta.to.shared.u64 t, %1; cvt.u32.u64 %0, t; }"
        : "=r"(a) : "l"(p));
    return a;
}
__device__ __forceinline__ void cpasync16(uint32_t dst, const void* src) {
    asm volatile("cp.async.cg.shared.global [%0], [%1], 16;\n"
                 :: "r"(dst), "l"(src) : "memory");
}
#define CP_COMMIT() asm volatile("cp.async.commit_group;\n" ::: "memory")
__device__ __forceinline__ void cp_wait(int n) {
    if (n == 0)      asm volatile("cp.async.wait_group 0;\n" ::: "memory");
    else if (n == 1) asm volatile("cp.async.wait_group 1;\n" ::: "memory");
    else             asm volatile("cp.async.wait_group 2;\n" ::: "memory");
}
__device__ __forceinline__ void ldm_x4(uint32_t& r0, uint32_t& r1,
                                       uint32_t& r2, uint32_t& r3, uint32_t addr) {
    asm volatile("ldmatrix.sync.aligned.m8n8.x4.shared.b16 {%0,%1,%2,%3}, [%4];"
                 : "=r"(r0), "=r"(r1), "=r"(r2), "=r"(r3) : "r"(addr));
}
__device__ __forceinline__ void mma_bf16(float* c, const uint32_t* a, const uint32_t* b) {
    asm volatile(
        "mma.sync.aligned.m16n8k16.row.col.f32.bf16.bf16.f32 "
        "{%0,%1,%2,%3}, {%4,%5,%6,%7}, {%8,%9}, {%0,%1,%2,%3};"
        : "+f"(c[0]), "+f"(c[1]), "+f"(c[2]), "+f"(c[3])
        : "r"(a[0]), "r"(a[1]), "r"(a[2]), "r"(a[3]), "r"(b[0]), "r"(b[1]));
}
__device__ __forceinline__ float gelu_f(float v) {
    return 0.5f * v * (1.0f + erff(v * 0.70710678118654752f));
}
// pack two floats into bf16x2 hi + residual lo
__device__ __forceinline__ void pack_hl(float x, float y, uint32_t& hi, uint32_t& lo) {
    __nv_bfloat162 h = __floats2bfloat162_rn(x, y);
    float hx = __bfloat162float(h.x), hy = __bfloat162float(h.y);
    __nv_bfloat162 l = __floats2bfloat162_rn(x - hx, y - hy);
    hi = *reinterpret_cast<uint32_t*>(&h);
    lo = *reinterpret_cast<uint32_t*>(&l);
}

// ================ convert kernels =============================================
__global__ void __launch_bounds__(256) convert_act(
    const float* __restrict__ x, __nv_bfloat16* __restrict__ hi,
    __nv_bfloat16* __restrict__ lo, int n4)
{
    int i = blockIdx.x * 256 + threadIdx.x;
    if (i >= n4) return;
    float4 v = reinterpret_cast<const float4*>(x)[i];
    uint32_t h0, l0, h1, l1;
    pack_hl(v.x, v.y, h0, l0);
    pack_hl(v.z, v.w, h1, l1);
    reinterpret_cast<uint32_t*>(hi)[i * 2 + 0] = h0;
    reinterpret_cast<uint32_t*>(hi)[i * 2 + 1] = h1;
    reinterpret_cast<uint32_t*>(lo)[i * 2 + 0] = l0;
    reinterpret_cast<uint32_t*>(lo)[i * 2 + 1] = l1;
}

// All 6 weight matrices of one layer, transposed to [N,K] bf16 hi/lo, one launch.
#define CW_BLOCKS 6912
__global__ void __launch_bounds__(256) convert_weights(
    const float* __restrict__ Wq, const float* __restrict__ Wk,
    const float* __restrict__ Wv, const float* __restrict__ Wo,
    const float* __restrict__ Wi, const float* __restrict__ Wo2,
    __nv_bfloat16* __restrict__ wqkvh, __nv_bfloat16* __restrict__ wqkvl,
    __nv_bfloat16* __restrict__ woh,  __nv_bfloat16* __restrict__ wol,
    __nv_bfloat16* __restrict__ wih,  __nv_bfloat16* __restrict__ wil,
    __nv_bfloat16* __restrict__ wo2h, __nv_bfloat16* __restrict__ wo2l)
{
    __shared__ float t[32][33];
    int b = blockIdx.x;
    const float* W; __nv_bfloat16 *Hd, *Ld; int K, N, tix;
    if (b < 1728) {
        int m = b / 576;
        W = (m == 0) ? Wq : (m == 1) ? Wk : Wv;
        Hd = wqkvh + (size_t)m * HH * HH; Ld = wqkvl + (size_t)m * HH * HH;
        K = HH; N = HH; tix = b % 576;
    } else if (b < 2304) {
        W = Wo; Hd = woh; Ld = wol; K = HH; N = HH; tix = b - 1728;
    } else if (b < 4608) {
        W = Wi; Hd = wih; Ld = wil; K = HH; N = FFD; tix = b - 2304;
    } else {
        W = Wo2; Hd = wo2h; Ld = wo2l; K = FFD; N = HH; tix = b - 4608;
    }
    int ntn = N / 32;
    int n0 = (tix % ntn) * 32, k0 = (tix / ntn) * 32;
    int tx = threadIdx.x & 31, ty = threadIdx.x >> 5;   // ty 0..7
    #pragma unroll
    for (int j = 0; j < 4; j++)
        t[ty + 8 * j][tx] = W[(size_t)(k0 + ty + 8 * j) * N + n0 + tx];
    __syncthreads();
    #pragma unroll
    for (int j = 0; j < 4; j++) {
        int n = ty + 8 * j;
        float v = t[tx][n];
        __nv_bfloat16 h = __float2bfloat16(v);
        __nv_bfloat16 l = __float2bfloat16(v - __bfloat162float(h));
        Hd[(size_t)(n0 + n) * K + k0 + tx] = h;
        Ld[(size_t)(n0 + n) * K + k0 + tx] = l;
    }
}

// V [B,S,H] fp32 -> per-head transposed Vt [bh][d][S] bf16 hi/lo
__global__ void __launch_bounds__(256) convert_vT(
    const float* __restrict__ v, __nv_bfloat16* __restrict__ vth,
    __nv_bfloat16* __restrict__ vtl)
{
    __shared__ float t[32][33];
    int bh = blockIdx.z;
    int b = bh / NHH, h = bh % NHH;
    int s0 = blockIdx.x * 32, d0 = blockIdx.y * 32;
    int tx = threadIdx.x & 31, ty = threadIdx.x >> 5;
    #pragma unroll
    for (int j = 0; j < 4; j++)
        t[ty + 8 * j][tx] = v[(size_t)(b * SSQ + s0 + ty + 8 * j) * HH + h * DHH + d0 + tx];
    __syncthreads();
    #pragma unroll
    for (int j = 0; j < 4; j++) {
        int d = ty + 8 * j;
        float val = t[tx][d];
        __nv_bfloat16 hb = __float2bfloat16(val);
        __nv_bfloat16 lb = __float2bfloat16(val - __bfloat162float(hb));
        size_t o = ((size_t)bh * DHH + d0 + d) * SSQ + s0 + tx;
        vth[o] = hb;
        vtl[o] = lb;
    }
}

// ================ mma.sync GEMM (bf16 split, 3 passes) ========================
// Tile 128x128x32, 8 warps, 3-stage cp.async pipeline, SINGLE sync per chunk.
// OUT=0: raw fp32 partial -> Cf + z*MMR*N (split-K via gridDim.z; no bias)
// OUT=1: bias + GELU -> bf16 hi/lo (Ch/Cl), stride N
// OUT=2: fused QKV (N=2304): region 0 -> Ch/Cl (Q), 1 -> C2h/C2l (K), 2 -> Cf (V)
static constexpr int GS_ROWB   = 80;
static constexpr int GS_TILE   = 128 * GS_ROWB;
static constexpr int GS_STAGE  = 2 * GS_TILE;
static constexpr int GS_STAGES = 3;
static constexpr int GT_SMEM   = GS_STAGES * GS_STAGE;  // 61440

template <int OUT>
__global__ void __launch_bounds__(256) gemm_tc(
    const __nv_bfloat16* __restrict__ Ah, const __nv_bfloat16* __restrict__ Al,
    const __nv_bfloat16* __restrict__ BhT, const __nv_bfloat16* __restrict__ BlT,
    const float* __restrict__ b0p, const float* __restrict__ b1p,
    const float* __restrict__ b2p,
    float* __restrict__ Cf,
    __nv_bfloat16* __restrict__ Ch, __nv_bfloat16* __restrict__ Cl,
    __nv_bfloat16* __restrict__ C2h, __nv_bfloat16* __restrict__ C2l,
    int K, int N)
{
    extern __shared__ char smem[];
    const uint32_t sbase = smem_u32(smem);
    const int tid = threadIdx.x;
    const int wid = tid >> 5, lane = tid & 31;
    const int warp_m = wid >> 2, warp_n = wid & 3;
    const int m0 = blockIdx.y * 128, n0 = blockIdx.x * 128;

    const int Kl = K / (int)gridDim.z;
    const int kb = (int)blockIdx.z * Kl;
    const int kch = Kl >> 5;
    const int nc = 3 * kch;
    const int seg = tid & 3;
    const int row0 = tid >> 2;

    auto loadChunk = [&](int c) {
        int p = c / kch;
        int kc = kb + ((c - p * kch) << 5);
        const __nv_bfloat16* aS = (p < 2) ? Ah : Al;
        const __nv_bfloat16* bS = (p == 1) ? BlT : BhT;
        uint32_t st = sbase + (uint32_t)(c % GS_STAGES) * GS_STAGE;
        #pragma unroll
        for (int i = 0; i < 2; i++) {
            int r = row0 + i * 64;
            cpasync16(st + (uint32_t)(r * GS_ROWB + seg * 16),
                      (const char*)(aS + (size_t)(m0 + r) * K + kc) + seg * 16);
        }
        #pragma unroll
        for (int i = 0; i < 2; i++) {
            int r = row0 + i * 64;
            cpasync16(st + GS_TILE + (uint32_t)(r * GS_ROWB + seg * 16),
                      (const char*)(bS + (size_t)(n0 + r) * K + kc) + seg * 16);
        }
        CP_COMMIT();
    };

    float acc[4][4][4];
    #pragma unroll
    for (int mt = 0; mt < 4; mt++)
        #pragma unroll
        for (int nt = 0; nt < 4; nt++)
            #pragma unroll
            for (int r = 0; r < 4; r++) acc[mt][nt][r] = 0.0f;

    loadChunk(0);
    loadChunk(1);

    const int a_row_in_tile = lane & 15;
    const int a_k8 = (lane >> 4) * 8;
    const int b_row_sel = (lane & 7) + ((lane >> 4) & 1) * 8;
    const int b_k8 = (lane & 8) ? 8 : 0;

    for (int c = 0; c < nc; c++) {
        // wait for chunk c (issued 2 iterations ago); chunk c+1 may stay in flight
        cp_wait((c + 1 < nc) ? 1 : 0);
        __syncthreads();
        // stage (c+2)%3 == (c-1)%3: all readers of it passed the barrier above
        if (c + 2 < nc) loadChunk(c + 2);

        uint32_t as = sbase + (uint32_t)(c % GS_STAGES) * GS_STAGE;
        uint32_t bs = as + GS_TILE;

        #pragma unroll
        for (int ks = 0; ks < 2; ks++) {
            uint32_t af[4][4], bf[4][2];
            #pragma unroll
            for (int mt = 0; mt < 4; mt++) {
                uint32_t addr = as
                    + (uint32_t)((warp_m * 64 + mt * 16 + a_row_in_tile) * GS_ROWB)
                    + (uint32_t)((ks * 16 + a_k8) * 2);
                ldm_x4(af[mt][0], af[mt][1], af[mt][2], af[mt][3], addr);
            }
            #pragma unroll
            for (int nt2 = 0; nt2 < 2; nt2++) {
                uint32_t addr = bs
                    + (uint32_t)((warp_n * 32 + nt2 * 16 + b_row_sel) * GS_ROWB)
                    + (uint32_t)((ks * 16 + b_k8) * 2);
                ldm_x4(bf[nt2 * 2][0], bf[nt2 * 2][1],
                       bf[nt2 * 2 + 1][0], bf[nt2 * 2 + 1][1], addr);
            }
            #pragma unroll
            for (int mt = 0; mt < 4; mt++)
                #pragma unroll
                for (int nt = 0; nt < 4; nt++)
                    mma_bf16(acc[mt][nt], af[mt], bf[nt]);
        }
    }

    const int cg = (lane & 3) * 2;
    const int rg = lane >> 2;

    if (OUT == 2) {
        const int reg = n0 / HH;               // 0:Q 1:K 2:V (tiles never straddle)
        const float* bp = (reg == 0) ? b0p : (reg == 1) ? b1p : b2p;
        __nv_bfloat16* dh = (reg == 0) ? Ch : C2h;
        __nv_bfloat16* dl = (reg == 0) ? Cl : C2l;
        #pragma unroll
        for (int nt = 0; nt < 4; nt++) {
            int col = n0 + warp_n * 32 + nt * 8 + cg;
            int cl = col - reg * HH;
            float bb0 = bp[cl], bb1 = bp[cl + 1];
            #pragma unroll
            for (int mt = 0; mt < 4; mt++) {
                int r1 = m0 + warp_m * 64 + mt * 16 + rg;
                float v0 = acc[mt][nt][0] + bb0;
                float v1 = acc[mt][nt][1] + bb1;
                float v2 = acc[mt][nt][2] + bb0;
                float v3 = acc[mt][nt][3] + bb1;
                if (reg == 2) {
                    float2 p0; p0.x = v0; p0.y = v1;
                    float2 p1; p1.x = v2; p1.y = v3;
                    *reinterpret_cast<float2*>(Cf + (size_t)r1 * HH + cl) = p0;
                    *reinterpret_cast<float2*>(Cf + (size_t)(r1 + 8) * HH + cl) = p1;
                } else {
                    uint32_t h0, l0, h1, l1;
                    pack_hl(v0, v1, h0, l0);
                    pack_hl(v2, v3, h1, l1);
                    *reinterpret_cast<uint32_t*>(dh + (size_t)r1 * HH + cl) = h0;
                    *reinterpret_cast<uint32_t*>(dl + (size_t)r1 * HH + cl) = l0;
                    *reinterpret_cast<uint32_t*>(dh + (size_t)(r1 + 8) * HH + cl) = h1;
                    *reinterpret_cast<uint32_t*>(dl + (size_t)(r1 + 8) * HH + cl) = l1;
                }
            }
        }
    } else if (OUT == 1) {
        #pragma unroll
        for (int nt = 0; nt < 4; nt++) {
            int col = n0 + warp_n * 32 + nt * 8 + cg;
            float bb0 = b0p[col], bb1 = b0p[col + 1];
            #pragma unroll
            for (int mt = 0; mt < 4; mt++) {
                int r1 = m0 + warp_m * 64 + mt * 16 + rg;
                float v0 = gelu_f(acc[mt][nt][0] + bb0);
                float v1 = gelu_f(acc[mt][nt][1] + bb1);
                float v2 = gelu_f(acc[mt][nt][2] + bb0);
                float v3 = gelu_f(acc[mt][nt][3] + bb1);
                uint32_t h0, l0, h1, l1;
                pack_hl(v0, v1, h0, l0);
                pack_hl(v2, v3, h1, l1);
                *reinterpret_cast<uint32_t*>(Ch + (size_t)r1 * N + col) = h0;
                *reinterpret_cast<uint32_t*>(Cl + (size_t)r1 * N + col) = l0;
                *reinterpret_cast<uint32_t*>(Ch + (size_t)(r1 + 8) * N + col) = h1;
                *reinterpret_cast<uint32_t*>(Cl + (size_t)(r1 + 8) * N + col) = l1;
            }
        }
    } else {
        // OUT == 0: raw split-K partial, no bias; slab per z
        float* Cz = Cf + (size_t)blockIdx.z * MMR * N;
        #pragma unroll
        for (int nt = 0; nt < 4; nt++) {
            int col = n0 + warp_n * 32 + nt * 8 + cg;
            #pragma unroll
            for (int mt = 0; mt < 4; mt++) {
                int r1 = m0 + warp_m * 64 + mt * 16 + rg;
                float2 p0; p0.x = acc[mt][nt][0]; p0.y = acc[mt][nt][1];
                float2 p1; p1.x = acc[mt][nt][2]; p1.y = acc[mt][nt][3];
                *reinterpret_cast<float2*>(Cz + (size_t)r1 * N + col) = p0;
                *reinterpret_cast<float2*>(Cz + (size_t)(r1 + 8) * N + col) = p1;
            }
        }
    }
}

// ================ flash attention (mma.sync, hi/lo split) =====================
// Single sync per KV tile: wait tile j -> barrier -> issue tile j+1 -> compute.
#define FA_KSTR 144
#define FA_VSTR 272
#define FA_OFF_KH 0
#define FA_OFF_KL 18432
#define FA_OFF_VH 36864
#define FA_OFF_VL 54272
#define FA_OFF_EXT 71680
#define FA_STAGE 72192
#define FA_SMEM (2*FA_STAGE)

__global__ void __launch_bounds__(256, 1) flash_attn(
    const __nv_bfloat16* __restrict__ qh, const __nv_bfloat16* __restrict__ ql,
    const __nv_bfloat16* __restrict__ kh, const __nv_bfloat16* __restrict__ kl,
    const __nv_bfloat16* __restrict__ vth, const __nv_bfloat16* __restrict__ vtl,
    const float* __restrict__ biasm, const float* __restrict__ mask,
    const float* __restrict__ bcp,
    __nv_bfloat16* __restrict__ ctxh, __nv_bfloat16* __restrict__ ctxl)
{
    extern __shared__ char smem[];
    const uint32_t sbase = smem_u32(smem);
    const int tid = threadIdx.x, wid = tid >> 5, lane = tid & 31;
    const int bh = blockIdx.y, b = bh / NHH, h = bh % NHH;
    const int q0 = blockIdx.x * 128;
    const float bc = bcp[0];

    const int b_row_sel = (lane & 7) + ((lane >> 4) & 1) * 8;
    const int b_k8 = (lane & 8) ? 8 : 0;
    const int colr = 2 * (lane & 3);
    const int rq = q0 + wid * 16 + (lane >> 2);

    uint32_t qhF[4][4], qlF[4][4];
    {
        const __nv_bfloat16* qh0 = qh + (size_t)(b * SSQ + rq) * HH + h * DHH;
        const __nv_bfloat16* ql0 = ql + (size_t)(b * SSQ + rq) * HH + h * DHH;
        const __nv_bfloat16* qh8 = qh0 + 8 * HH;
        const __nv_bfloat16* ql8 = ql0 + 8 * HH;
        #pragma unroll
        for (int f = 0; f < 4; f++) {
            int k = f * 16 + colr;
            qhF[f][0] = *reinterpret_cast<const uint32_t*>(qh0 + k);
            qhF[f][1] = *reinterpret_cast<const uint32_t*>(qh8 + k);
            qhF[f][2] = *reinterpret_cast<const uint32_t*>(qh0 + k + 8);
            qhF[f][3] = *reinterpret_cast<const uint32_t*>(qh8 + k + 8);
            qlF[f][0] = *reinterpret_cast<const uint32_t*>(ql0 + k);
            qlF[f][1] = *reinterpret_cast<const uint32_t*>(ql8 + k);
            qlF[f][2] = *reinterpret_cast<const uint32_t*>(ql0 + k + 8);
            qlF[f][3] = *reinterpret_cast<const uint32_t*>(ql8 + k + 8);
        }
    }

    auto loadTile = [&](int j) {
        uint32_t st = sbase + (uint32_t)(j & 1) * FA_STAGE;
        int k0 = j * 128;
        #pragma unroll
        for (int i = 0; i < 4; i++) {
            int idx = tid + i * 256;
            int row = idx >> 3, seg = idx & 7;
            size_t go = (size_t)(b * SSQ + k0 + row) * HH + h * DHH + seg * 8;
            cpasync16(st + FA_OFF_KH + (uint32_t)(row * FA_KSTR + seg * 16), kh + go);
            cpasync16(st + FA_OFF_KL + (uint32_t)(row * FA_KSTR + seg * 16), kl + go);
        }
        #pragma unroll
        for (int i = 0; i < 4; i++) {
            int idx = tid + i * 256;
            int d = idx >> 4, seg = idx & 15;
            size_t go = ((size_t)bh * DHH + d) * SSQ + k0 + seg * 8;
            cpasync16(st + FA_OFF_VH + (uint32_t)(d * FA_VSTR + seg * 16), vth + go);
            cpasync16(st + FA_OFF_VL + (uint32_t)(d * FA_VSTR + seg * 16), vtl + go);
        }
        if (tid < 128) {
            float mv = mask[b * SSQ + k0 + tid];
            *reinterpret_cast<float*>(smem + (size_t)(j & 1) * FA_STAGE + FA_OFF_EXT + tid * 4)
                = (1.0f - mv) * NEGV;
        }
        CP_COMMIT();
    };

    float m0 = -INFINITY, m1 = -INFINITY, l0 = 0.0f, l1 = 0.0f;
    float oac[8][4];
    #pragma unroll
    for (int nt = 0; nt < 8; nt++)
        #pragma unroll
        for (int r = 0; r < 4; r++) oac[nt][r] = 0.0f;

    const int NT = SSQ / 128;   // 16
    loadTile(0);

    for (int j = 0; j < NT; j++) {
        cp_wait(0);
        __syncthreads();
        // stage (j+1)&1: readers of it (iteration j-1) all passed the barrier
        if (j + 1 < NT) loadTile(j + 1);

        uint32_t st = sbase + (uint32_t)(j & 1) * FA_STAGE;
        const float* ext_s = reinterpret_cast<const float*>(
            smem + (size_t)(j & 1) * FA_STAGE + FA_OFF_EXT);
        const int k0 = j * 128;

        float sac[16][4];
        #pragma unroll
        for (int t = 0; t < 16; t++)
            #pragma unroll
            for (int r = 0; r < 4; r++) sac[t][r] = 0.0f;

        #pragma unroll
        for (int pass = 0; pass < 3; pass++) {
            const uint32_t (*AF)[4] = (pass == 2) ? qlF : qhF;
            const uint32_t koff = (pass == 1) ? FA_OFF_KL : FA_OFF_KH;
            #pragma unroll
            for (int ks = 0; ks < 4; ks++) {
                #pragma unroll
                for (int half = 0; half < 2; half++) {
                    uint32_t bb[8][2];
                    #pragma unroll
                    for (int q2 = 0; q2 < 4; q2++) {
                        int nt2 = half * 4 + q2;
                        uint32_t addr = st + koff
                            + (uint32_t)((nt2 * 16 + b_row_sel) * FA_KSTR)
                            + (uint32_t)((ks * 16 + b_k8) * 2);
                        ldm_x4(bb[q2 * 2][0], bb[q2 * 2][1],
                               bb[q2 * 2 + 1][0], bb[q2 * 2 + 1][1], addr);
                    }
                    #pragma unroll
                    for (int t = 0; t < 8; t++)
                        mma_bf16(sac[half * 8 + t], AF[ks], bb[t]);
                }
            }
        }

        #pragma unroll
        for (int t = 0; t < 16; t++) {
            int c = k0 + t * 8 + colr;
            float2 bz0 = *reinterpret_cast<const float2*>(biasm + (size_t)rq * SSQ + c);
            float2 bz1 = *reinterpret_cast<const float2*>(biasm + (size_t)(rq + 8) * SSQ + c);
            float e0 = ext_s[t * 8 + colr], e1 = ext_s[t * 8 + colr + 1];
            sac[t][0] = fmaf(bc, bz0.x, sac[t][0] * 0.125f) + e0;
            sac[t][1] = fmaf(bc, bz0.y, sac[t][1] * 0.125f) + e1;
            sac[t][2] = fmaf(bc, bz1.x, sac[t][2] * 0.125f) + e0;
            sac[t][3] = fmaf(bc, bz1.y, sac[t][3] * 0.125f) + e1;
        }

        float mx0 = -INFINITY, mx1 = -INFINITY;
        #pragma unroll
        for (int t = 0; t < 16; t++) {
            mx0 = fmaxf(mx0, fmaxf(sac[t][0], sac[t][1]));
            mx1 = fmaxf(mx1, fmaxf(sac[t][2], sac[t][3]));
        }
        mx0 = fmaxf(mx0, __shfl_xor_sync(0xffffffffu, mx0, 1));
        mx0 = fmaxf(mx0, __shfl_xor_sync(0xffffffffu, mx0, 2));
        mx1 = fmaxf(mx1, __shfl_xor_sync(0xffffffffu, mx1, 1));
        mx1 = fmaxf(mx1, __shfl_xor_sync(0xffffffffu, mx1, 2));

        float mn0 = fmaxf(m0, mx0), mn1 = fmaxf(m1, mx1);
        float a0 = __expf(m0 - mn0), a1 = __expf(m1 - mn1);
        float s0 = 0.0f, s1 = 0.0f;
        #pragma unroll
        for (int t = 0; t < 16; t++) {
            sac[t][0] = __expf(sac[t][0] - mn0);
            sac[t][1] = __expf(sac[t][1] - mn0);
            sac[t][2] = __expf(sac[t][2] - mn1);
            sac[t][3] = __expf(sac[t][3] - mn1);
            s0 += sac[t][0] + sac[t][1];
            s1 += sac[t][2] + sac[t][3];
        }
        l0 = l0 * a0 + s0;
        l1 = l1 * a1 + s1;
        #pragma unroll
        for (int nt = 0; nt < 8; nt++) {
            oac[nt][0] *= a0; oac[nt][1] *= a0;
            oac[nt][2] *= a1; oac[nt][3] *= a1;
        }
        m0 = mn0; m1 = mn1;

        uint32_t ph[8][4], pl[8][4];
        #pragma unroll
        for (int f = 0; f < 8; f++) {
            int t0 = 2 * f, t1 = 2 * f + 1;
            pack_hl(sac[t0][0], sac[t0][1], ph[f][0], pl[f][0]);
            pack_hl(sac[t0][2], sac[t0][3], ph[f][1], pl[f][1]);
            pack_hl(sac[t1][0], sac[t1][1], ph[f][2], pl[f][2]);
            pack_hl(sac[t1][2], sac[t1][3], ph[f][3], pl[f][3]);
        }

        #pragma unroll
        for (int pass = 0; pass < 3; pass++) {
            const uint32_t (*PF)[4] = (pass == 2) ? pl : ph;
            const uint32_t voff = (pass == 1) ? FA_OFF_VL : FA_OFF_VH;
            #pragma unroll
            for (int f = 0; f < 8; f++) {
                uint32_t vb[8][2];
                #pragma unroll
                for (int q2 = 0; q2 < 4; q2++) {
                    uint32_t addr = st + voff
                        + (uint32_t)((q2 * 16 + b_row_sel) * FA_VSTR)
                        + (uint32_t)((f * 16 + b_k8) * 2);
                    ldm_x4(vb[q2 * 2][0], vb[q2 * 2][1],
                           vb[q2 * 2 + 1][0], vb[q2 * 2 + 1][1], addr);
                }
                #pragma unroll
                for (int nt = 0; nt < 8; nt++)
                    mma_bf16(oac[nt], PF[f], vb[nt]);
            }
        }
    }

    l0 += __shfl_xor_sync(0xffffffffu, l0, 1);
    l0 += __shfl_xor_sync(0xffffffffu, l0, 2);
    l1 += __shfl_xor_sync(0xffffffffu, l1, 1);
    l1 += __shfl_xor_sync(0xffffffffu, l1, 2);
    float i0 = 1.0f / l0, i1 = 1.0f / l1;

    #pragma unroll
    for (int nt = 0; nt < 8; nt++) {
        int col = h * DHH + nt * 8 + colr;
        uint32_t h0, lo0, h1, lo1;
        pack_hl(oac[nt][0] * i0, oac[nt][1] * i0, h0, lo0);
        pack_hl(oac[nt][2] * i1, oac[nt][3] * i1, h1, lo1);
        size_t o0 = (size_t)(b * SSQ + rq) * HH + col;
        size_t o1 = (size_t)(b * SSQ + rq + 8) * HH + col;
        *reinterpret_cast<uint32_t*>(ctxh + o0) = h0;
        *reinterpret_cast<uint32_t*>(ctxl + o0) = lo0;
        *reinterpret_cast<uint32_t*>(ctxh + o1) = h1;
        *reinterpret_cast<uint32_t*>(ctxl + o1) = lo1;
    }
}

// ---------------- block reduction ---------------------------------------------
__device__ __forceinline__ float blockReduceSum(float x) {
    __shared__ float sh[8];
    __syncthreads();
    int lane = threadIdx.x & 31, w = threadIdx.x >> 5;
    #pragma unroll
    for (int o = 16; o > 0; o >>= 1) x += __shfl_xor_sync(0xffffffffu, x, o);
    if (lane == 0) sh[w] = x;
    __syncthreads();
    if (w == 0) {
        x = (lane < 8) ? sh[lane] : 0.0f;
        #pragma unroll
        for (int o = 4; o > 0; o >>= 1) x += __shfl_xor_sync(0xffffffffu, x, o);
        if (lane == 0) sh[0] = x;
    }
    __syncthreads();
    return sh[0];
}

// --------- split-K sum + bias + residual + LayerNorm (+ hi/lo emit) -----------
__global__ void __launch_bounds__(256) add_ln2(
    const float* __restrict__ a0, const float* __restrict__ a1,
    const float* __restrict__ bias, const float* __restrict__ res,
    const float* __restrict__ g, const float* __restrict__ bta,
    float* __restrict__ out,
    __nv_bfloat16* __restrict__ oh, __nv_bfloat16* __restrict__ ol)
{
    const int row = blockIdx.x;
    const float* a0p = a0 + (size_t)row * HH;
    const float* a1p = a1 + (size_t)row * HH;
    const float* rp  = res + (size_t)row * HH;
    const int tid = threadIdx.x;

    float v[3];
    float s = 0.0f;
    #pragma unroll
    for (int l = 0; l < 3; l++) {
        int c = tid + l * 256;
        v[l] = a0p[c] + a1p[c] + bias[c] + rp[c];
        s += v[l];
    }
    s = blockReduceSum(s);
    const float mu = s * (1.0f / HH);

    float var = 0.0f;
    #pragma unroll
    for (int l = 0; l < 3; l++) {
        float d = v[l] - mu;
        var += d * d;
    }
    var = blockReduceSum(var);
    const float inv = rsqrtf(var * (1.0f / HH) + 1e-12f);

    float* op = out + (size_t)row * HH;
    __nv_bfloat16* ohp = oh + (size_t)row * HH;
    __nv_bfloat16* olp = ol + (size_t)row * HH;
    #pragma unroll
    for (int l = 0; l < 3; l++) {
        int c = tid + l * 256;
        float y = (v[l] - mu) * inv * g[c] + bta[c];
        op[c] = y;
        __nv_bfloat16 hb = __float2bfloat16(y);
        ohp[c] = hb;
        olp[c] = __float2bfloat16(y - __bfloat162float(hb));
    }
}

// ---------------- host orchestration ------------------------------------------
extern "C" void kernel_launch(void* const* d_in, const int* in_sizes, int n_in,
                              void* d_out, int out_size)
{
    (void)in_sizes; (void)n_in; (void)out_size;

    const float* hidden    = (const float*)d_in[0];
    const float* mask      = (const float*)d_in[1];
    const float* biasm     = (const float*)d_in[2];
    const float* bias_coef = (const float*)d_in[3];
    const float* Wq  = (const float*)d_in[4];
    const float* bq  = (const float*)d_in[5];
    const float* Wk  = (const float*)d_in[6];
    const float* bk  = (const float*)d_in[7];
    const float* Wv  = (const float*)d_in[8];
    const float* bv  = (const float*)d_in[9];
    const float* Wo  = (const float*)d_in[10];
    const float* bo  = (const float*)d_in[11];
    const float* ln1g= (const float*)d_in[12];
    const float* ln1b= (const float*)d_in[13];
    const float* Wi  = (const float*)d_in[14];
    const float* bi  = (const float*)d_in[15];
    const float* Wo2 = (const float*)d_in[16];
    const float* bo2 = (const float*)d_in[17];
    const float* ln2g= (const float*)d_in[18];
    const float* ln2b= (const float*)d_in[19];
    float* out = (float*)d_out;

    cudaFuncSetAttribute(gemm_tc<0>, cudaFuncAttributeMaxDynamicSharedMemorySize, GT_SMEM);
    cudaFuncSetAttribute(gemm_tc<1>, cudaFuncAttributeMaxDynamicSharedMemorySize, GT_SMEM);
    cudaFuncSetAttribute(gemm_tc<2>, cudaFuncAttributeMaxDynamicSharedMemorySize, GT_SMEM);
    cudaFuncSetAttribute(flash_attn, cudaFuncAttributeMaxDynamicSharedMemorySize, FA_SMEM);

    float *vP, *attnP, *xmidP, *ffnP, *xP;
    cudaGetSymbolAddress((void**)&vP,    g_v);
    cudaGetSymbolAddress((void**)&attnP, g_attn);
    cudaGetSymbolAddress((void**)&xmidP, g_xmid);
    cudaGetSymbolAddress((void**)&ffnP,  g_ffn);
    cudaGetSymbolAddress((void**)&xP,    g_x);
    __nv_bfloat16 *xhP,*xlP,*qhP,*qlP,*khP,*klP,*ctxhP,*ctxlP,*xmhP,*xmlP,*inthP,*intlP,*vthP,*vtlP;
    cudaGetSymbolAddress((void**)&xhP,   g_xh);
    cudaGetSymbolAddress((void**)&xlP,   g_xl);
    cudaGetSymbolAddress((void**)&qhP,   g_qh);
    cudaGetSymbolAddress((void**)&qlP,   g_ql);
    cudaGetSymbolAddress((void**)&khP,   g_kh);
    cudaGetSymbolAddress((void**)&klP,   g_kl);
    cudaGetSymbolAddress((void**)&ctxhP, g_ctxh);
    cudaGetSymbolAddress((void**)&ctxlP, g_ctxl);
    cudaGetSymbolAddress((void**)&xmhP,  g_xmh);
    cudaGetSymbolAddress((void**)&xmlP,  g_xml);
    cudaGetSymbolAddress((void**)&inthP, g_inth);
    cudaGetSymbolAddress((void**)&intlP, g_intl);
    cudaGetSymbolAddress((void**)&vthP,  g_vth);
    cudaGetSymbolAddress((void**)&vtlP,  g_vtl);
    __nv_bfloat16 *wqkvh,*wqkvl,*wohP,*wolP,*wihP,*wilP,*wo2hP,*wo2lP;
    cudaGetSymbolAddress((void**)&wqkvh, g_wqkvh);
    cudaGetSymbolAddress((void**)&wqkvl, g_wqkvl);
    cudaGetSymbolAddress((void**)&wohP,  g_woh);
    cudaGetSymbolAddress((void**)&wolP,  g_wol);
    cudaGetSymbolAddress((void**)&wihP,  g_wih);
    cudaGetSymbolAddress((void**)&wilP,  g_wil);
    cudaGetSymbolAddress((void**)&wo2hP, g_wo2h);
    cudaGetSymbolAddress((void**)&wo2lP, g_wo2l);

    // layer-0 input convert
    {
        int n4 = MMR * HH / 4;
        convert_act<<<(n4 + 255) / 256, 256>>>(hidden, xhP, xlP, n4);
    }

    const float* xres = hidden;
    for (int i = 0; i < LLN; i++) {
        const float* Wq_i  = Wq  + (size_t)i * HH * HH;
        const float* Wk_i  = Wk  + (size_t)i * HH * HH;
        const float* Wv_i  = Wv  + (size_t)i * HH * HH;
        const float* Wo_i  = Wo  + (size_t)i * HH * HH;
        const float* Wi_i  = Wi  + (size_t)i * HH * FFD;
        const float* Wo2_i = Wo2 + (size_t)i * FFD * HH;

        // all 6 weight matrices in one launch
        convert_weights<<<CW_BLOCKS, 256>>>(
            Wq_i, Wk_i, Wv_i, Wo_i, Wi_i, Wo2_i,
            wqkvh, wqkvl, wohP, wolP, wihP, wilP, wo2hP, wo2lP);

        // fused QKV projection
        gemm_tc<2><<<dim3(3*HH/128, MMR/128, 1), 256, GT_SMEM>>>(
            xhP, xlP, wqkvh, wqkvl,
            bq + i*HH, bk + i*HH, bv + i*HH,
            vP, qhP, qlP, khP, klP, HH, 3*HH);

        convert_vT<<<dim3(SSQ/32, DHH/32, BB*NHH), 256>>>(vP, vthP, vtlP);

        flash_attn<<<dim3(SSQ/128, BB*NHH), 256, FA_SMEM>>>(
            qhP, qlP, khP, klP, vthP, vtlP, biasm, mask, bias_coef, ctxhP, ctxlP);

        // output projection, split-K=2 (raw partials into g_attn's two slabs)
        gemm_tc<0><<<dim3(HH/128, MMR/128, 2), 256, GT_SMEM>>>(
            ctxhP, ctxlP, wohP, wolP,
            nullptr, nullptr, nullptr,
            attnP, nullptr, nullptr, nullptr, nullptr, HH, HH);
        add_ln2<<<MMR, 256>>>(attnP, attnP + (size_t)MMR*HH,
                              bo + i*HH, xres, ln1g + i*HH, ln1b + i*HH,
                              xmidP, xmhP, xmlP);

        // FFN
        gemm_tc<1><<<dim3(FFD/128, MMR/128, 1), 256, GT_SMEM>>>(
            xmhP, xmlP, wihP, wilP,
            bi + i*FFD, nullptr, nullptr,
            nullptr, inthP, intlP, nullptr, nullptr, HH, FFD);
        gemm_tc<0><<<dim3(HH/128, MMR/128, 2), 256, GT_SMEM>>>(
            inthP, intlP, wo2hP, wo2lP,
            nullptr, nullptr, nullptr,
            ffnP, nullptr, nullptr, nullptr, nullptr, FFD, HH);

        float* xo = (i == LLN - 1) ? out : xP;
        add_ln2<<<MMR, 256>>>(ffnP, ffnP + (size_t)MMR*HH,
                              bo2 + i*HH, xmidP, ln2g + i*HH, ln2b + i*HH,
                              xo, xhP, xlP);
        xres = xo;
    }
}